// round 8
// baseline (speedup 1.0000x reference)
#include <cuda_runtime.h>

// Problem constants
#define B       8
#define C       64
#define G       8
#define FPG     8
#define OCPG    8
#define REPD    32
#define H       256
#define Wd      256
#define PLANE   (H * Wd)             // 65536
#define PLANE4  (PLANE / 4)          // 16384
#define NWTS    (OCPG * 9)           // 72

// Strip: full width x 32 rows, processed as 2 chunks of 16 rows
#define TY      16
#define HS      32
#define NTHR    256
#define SROWS   (HS + 2)             // 34 rows resident in smem
#define SSTR    260                  // floats per smem row (16B aligned)
#define SSTR4   (SSTR / 4)

// ---------------------------------------------------------------------------
// compute one 16-row chunk; S/Sx/Sw bases pre-offset so row 0 = top halo row
// ---------------------------------------------------------------------------
__device__ __forceinline__ void compute_chunk(const float* __restrict__ S,
                                              const float* __restrict__ Sx,
                                              const float* __restrict__ Sw,
                                              const float* __restrict__ w0,
                                              const float* __restrict__ w1,
                                              float4* __restrict__ o0,
                                              int q, int qm, int qp) {
    float4* o1 = o0 + 4 * PLANE4;    // channel p+4

    float a0,a1,a2,a3,a4,a5, m0,m1,m2,m3,m4,m5;
    {
        const float4 v = *(const float4*)&S[0 * SSTR + 4 * q];
        const float l = Sw[0 * 64 + qm], rr = Sx[0 * 64 + qp];
        a1 = v.x; a2 = v.y; a3 = v.z; a4 = v.w;
        a0 = (q == 0)  ? v.y : l;
        a5 = (q == 63) ? v.z : rr;
    }
    {
        const float4 v = *(const float4*)&S[1 * SSTR + 4 * q];
        const float l = Sw[1 * 64 + qm], rr = Sx[1 * 64 + qp];
        m1 = v.x; m2 = v.y; m3 = v.z; m4 = v.w;
        m0 = (q == 0)  ? v.y : l;
        m5 = (q == 63) ? v.z : rr;
    }

#pragma unroll
    for (int r = 0; r < TY; ++r) {
        const float4 v = *(const float4*)&S[(r + 2) * SSTR + 4 * q];
        const float l = Sw[(r + 2) * 64 + qm], rr = Sx[(r + 2) * 64 + qp];
        const float c1 = v.x, c2 = v.y, c3 = v.z, c4 = v.w;
        const float c0 = (q == 0)  ? v.y : l;
        const float c5 = (q == 63) ? v.z : rr;

        float4 u, s;
        u.x =      w0[0]*a0;          s.x =      w1[0]*a0;
        u.x = fmaf(w0[1],a1,u.x);     s.x = fmaf(w1[1],a1,s.x);
        u.x = fmaf(w0[2],a2,u.x);     s.x = fmaf(w1[2],a2,s.x);
        u.x = fmaf(w0[3],m0,u.x);     s.x = fmaf(w1[3],m0,s.x);
        u.x = fmaf(w0[4],m1,u.x);     s.x = fmaf(w1[4],m1,s.x);
        u.x = fmaf(w0[5],m2,u.x);     s.x = fmaf(w1[5],m2,s.x);
        u.x = fmaf(w0[6],c0,u.x);     s.x = fmaf(w1[6],c0,s.x);
        u.x = fmaf(w0[7],c1,u.x);     s.x = fmaf(w1[7],c1,s.x);
        u.x = fmaf(w0[8],c2,u.x);     s.x = fmaf(w1[8],c2,s.x);

        u.y =      w0[0]*a1;          s.y =      w1[0]*a1;
        u.y = fmaf(w0[1],a2,u.y);     s.y = fmaf(w1[1],a2,s.y);
        u.y = fmaf(w0[2],a3,u.y);     s.y = fmaf(w1[2],a3,s.y);
        u.y = fmaf(w0[3],m1,u.y);     s.y = fmaf(w1[3],m1,s.y);
        u.y = fmaf(w0[4],m2,u.y);     s.y = fmaf(w1[4],m2,s.y);
        u.y = fmaf(w0[5],m3,u.y);     s.y = fmaf(w1[5],m3,s.y);
        u.y = fmaf(w0[6],c1,u.y);     s.y = fmaf(w1[6],c1,s.y);
        u.y = fmaf(w0[7],c2,u.y);     s.y = fmaf(w1[7],c2,s.y);
        u.y = fmaf(w0[8],c3,u.y);     s.y = fmaf(w1[8],c3,s.y);

        u.z =      w0[0]*a2;          s.z =      w1[0]*a2;
        u.z = fmaf(w0[1],a3,u.z);     s.z = fmaf(w1[1],a3,s.z);
        u.z = fmaf(w0[2],a4,u.z);     s.z = fmaf(w1[2],a4,s.z);
        u.z = fmaf(w0[3],m2,u.z);     s.z = fmaf(w1[3],m2,s.z);
        u.z = fmaf(w0[4],m3,u.z);     s.z = fmaf(w1[4],m3,s.z);
        u.z = fmaf(w0[5],m4,u.z);     s.z = fmaf(w1[5],m4,s.z);
        u.z = fmaf(w0[6],c2,u.z);     s.z = fmaf(w1[6],c2,s.z);
        u.z = fmaf(w0[7],c3,u.z);     s.z = fmaf(w1[7],c3,s.z);
        u.z = fmaf(w0[8],c4,u.z);     s.z = fmaf(w1[8],c4,s.z);

        u.w =      w0[0]*a3;          s.w =      w1[0]*a3;
        u.w = fmaf(w0[1],a4,u.w);     s.w = fmaf(w1[1],a4,s.w);
        u.w = fmaf(w0[2],a5,u.w);     s.w = fmaf(w1[2],a5,s.w);
        u.w = fmaf(w0[3],m3,u.w);     s.w = fmaf(w1[3],m3,s.w);
        u.w = fmaf(w0[4],m4,u.w);     s.w = fmaf(w1[4],m4,s.w);
        u.w = fmaf(w0[5],m5,u.w);     s.w = fmaf(w1[5],m5,s.w);
        u.w = fmaf(w0[6],c3,u.w);     s.w = fmaf(w1[6],c3,s.w);
        u.w = fmaf(w0[7],c4,u.w);     s.w = fmaf(w1[7],c4,s.w);
        u.w = fmaf(w0[8],c5,u.w);     s.w = fmaf(w1[8],c5,s.w);

        o0[(size_t)r * 64] = u;
        o1[(size_t)r * 64] = s;

        a0=m0; a1=m1; a2=m2; a3=m3; a4=m4; a5=m5;
        m0=c0; m1=c1; m2=c2; m3=c3; m4=c4; m5=c5;
    }
}

// ---------------------------------------------------------------------------
// Pipelined strip kernel: grid (H/HS, B*G), block 256.
// Prolog loads rows [-1,17); chunk-1 rows [17,33) are prefetched into
// registers while chunk 0 computes, then stored and consumed.
// ---------------------------------------------------------------------------
__global__ __launch_bounds__(NTHR, 3)
void dyn_conv(const float* __restrict__ x,
              const float* __restrict__ rep,
              const float* __restrict__ Wm,
              float* __restrict__ out) {
    const int bg = blockIdx.y;
    const int b  = bg >> 3;
    const int g  = bg & 7;
    const int y0 = blockIdx.x * HS;
    const int t  = threadIdx.x;

    __shared__ __align__(16) float S[SROWS * SSTR];
    __shared__ float Sx[SROWS * 64];
    __shared__ float Sw[SROWS * 64];
    __shared__ float wsh[NWTS];
    __shared__ float rsh[REPD];

    // ---- weight generation ----
    if (t < REPD) rsh[t] = rep[b * REPD + t];
    __syncthreads();
    if (t < NWTS) {
        const float* wrow = Wm + (size_t)(g * NWTS + t) * REPD;
        float acc = 0.f;
#pragma unroll
        for (int j = 0; j < REPD; ++j) acc = fmaf(rsh[j], wrow[j], acc);
        wsh[t] = acc > 0.f ? acc : 0.1f * acc;
    }

    const float4* xb = (const float4*)x + ((size_t)(b * C + g * FPG)) * PLANE4;

    // ---- prolog: channel-sum rows [-1, 17) -> smem rows 0..17 ----
#pragma unroll
    for (int idx = t; idx < 18 * 64; idx += NTHR) {      // 1152 float4s
        const int r  = idx >> 6;
        const int q4 = idx & 63;
        int yy = y0 - 1 + r;
        yy = (yy < 0) ? -yy : yy;
        yy = (yy >= H) ? (2 * H - 2 - yy) : yy;
        const float4* p = xb + (size_t)yy * 64 + q4;
        float4 s = p[0];
#pragma unroll
        for (int ch = 1; ch < FPG; ++ch) {
            const float4 v = p[(size_t)ch * PLANE4];
            s.x += v.x; s.y += v.y; s.z += v.z; s.w += v.w;
        }
        ((float4*)S)[r * SSTR4 + q4] = s;
        Sx[r * 64 + q4] = s.x;
        Sw[r * 64 + q4] = s.w;
    }
    __syncthreads();

    // ---- prefetch rows [17, 33) into registers (issued before compute) ----
    float4 pf[4];
#pragma unroll
    for (int j = 0; j < 4; ++j) {
        const int qidx = t + j * NTHR;                   // 0..1023
        const int r  = qidx >> 6;                        // 0..15
        const int q4 = qidx & 63;
        int yy = y0 + 17 + r;
        yy = (yy >= H) ? (2 * H - 2 - yy) : yy;
        const float4* p = xb + (size_t)yy * 64 + q4;
        float4 s = p[0];
#pragma unroll
        for (int ch = 1; ch < FPG; ++ch) {
            const float4 v = p[(size_t)ch * PLANE4];
            s.x += v.x; s.y += v.y; s.z += v.z; s.w += v.w;
        }
        pf[j] = s;
    }

    // ---- phase-2 thread mapping ----
    const int q  = t & 63;
    const int p  = t >> 6;
    const int qm = (q == 0)  ? 0  : q - 1;
    const int qp = (q == 63) ? 63 : q + 1;

    float w0[9], w1[9];
#pragma unroll
    for (int k = 0; k < 9; ++k) {
        w0[k] = wsh[p * 9 + k];
        w1[k] = wsh[(p + 4) * 9 + k];
    }

    float4* obase = (float4*)(out + ((size_t)(b * C + g * OCPG + p)) * PLANE
                                  + (size_t)y0 * Wd) + q;

    // ---- compute chunk 0 (rows y0..y0+16) while prefetch is in flight ----
    compute_chunk(S, Sx, Sw, w0, w1, obase, q, qm, qp);

    // ---- commit prefetched rows 17..33 -> smem rows 18..33 ----
#pragma unroll
    for (int j = 0; j < 4; ++j) {
        const int qidx = t + j * NTHR;
        const int r  = (qidx >> 6) + 18;
        const int q4 = qidx & 63;
        ((float4*)S)[r * SSTR4 + q4] = pf[j];
        Sx[r * 64 + q4] = pf[j].x;
        Sw[r * 64 + q4] = pf[j].w;
    }
    __syncthreads();

    // ---- compute chunk 1 (rows y0+16..y0+32) ----
    compute_chunk(S + TY * SSTR, Sx + TY * 64, Sw + TY * 64,
                  w0, w1, obase + (size_t)TY * 64, q, qm, qp);
}

// ---------------------------------------------------------------------------
extern "C" void kernel_launch(void* const* d_in, const int* in_sizes, int n_in,
                              void* d_out, int out_size) {
    const float* x   = (const float*)d_in[0];
    const float* rep = (const float*)d_in[1];
    const float* Wm  = (const float*)d_in[2];
    float* out = (float*)d_out;

    dim3 grid(H / HS, B * G);
    dyn_conv<<<grid, NTHR>>>(x, rep, Wm, out);
}